// round 9
// baseline (speedup 1.0000x reference)
#include <cuda_runtime.h>
#include <cstdint>

#define NB    131072
#define DC    1029
#define TT    1024
#define H1N   64
#define H2N   32
#define KTOT  1028
#define KC    32
#define NCH   33              // 33*32 = 1056 padded K
#define MT    128             // rows per CTA
#define NT    256             // 8 warps, each m16 x n64
#define NSTG  4
#define B_ST  8192            // bytes per B stage (2048 floats)
#define SMEM_DYN 34816        // max(B ring 32768, h staging 128*68*4)
#define H_STRIDE 68

__device__ float g_row_mean[TT];
__device__ __align__(16) float g_w1f[NCH * 2048];   // pre-packed, pre-swizzled tf32 B frags

// ---------------- helpers ----------------
__device__ __forceinline__ uint32_t tf32r(float f) {
    uint32_t u;
    asm("cvt.rna.tf32.f32 %0, %1;" : "=r"(u) : "f"(f));
    return u;
}
__device__ __forceinline__ void mma_tf32(float* d, const uint32_t* a, uint32_t b0, uint32_t b1) {
    asm volatile(
        "mma.sync.aligned.m16n8k8.row.col.f32.tf32.tf32.f32 "
        "{%0,%1,%2,%3}, {%4,%5,%6,%7}, {%8,%9}, {%0,%1,%2,%3};"
        : "+f"(d[0]), "+f"(d[1]), "+f"(d[2]), "+f"(d[3])
        : "r"(a[0]), "r"(a[1]), "r"(a[2]), "r"(a[3]), "r"(b0), "r"(b1));
}
__device__ __forceinline__ uint32_t smem_u32(const void* p) {
    uint32_t a;
    asm("{ .reg .u64 t; cvta.to.shared.u64 t, %1; cvt.u32.u64 %0, t; }" : "=r"(a) : "l"(p));
    return a;
}
__device__ __forceinline__ void cp16(uint32_t dst, const float* src) {
    asm volatile("cp.async.ca.shared.global [%0], [%1], 16;"
                 :: "r"(dst), "l"(__cvta_generic_to_global(src)) : "memory");
}

// ---------------- merged prep kernel (identical pack layout to R5) ----------------
__global__ void prep_kernel(const float* __restrict__ con, const float* __restrict__ w1) {
    if (blockIdx.x < TT) {
        int t = blockIdx.x;
        float s = 0.f;
        for (int j = threadIdx.x; j < TT; j += blockDim.x)
            s += con[(size_t)t * TT + j];
#pragma unroll
        for (int o = 16; o > 0; o >>= 1) s += __shfl_down_sync(0xffffffffu, s, o);
        __shared__ float red[8];
        if ((threadIdx.x & 31) == 0) red[threadIdx.x >> 5] = s;
        __syncthreads();
        if (threadIdx.x == 0) {
            float tot = 0.f;
#pragma unroll
            for (int w = 0; w < 8; w++) tot += red[w];
            g_row_mean[t] = tot * (1.0f / (float)TT);
        }
    } else {
        int idx = (blockIdx.x - TT) * blockDim.x + threadIdx.x;
        if (idx >= NCH * 2048) return;
        int ch = idx >> 11;
        int w  = idx & 2047;
        int g  = w >> 2, e = w & 3;
        int kt = g >> 7;
        int lane = (g >> 2) & 31;
        int s = g & 3;
        int i = s ^ (lane & 3) ^ ((lane >> 2) & 1);
        int nt = 2 * i + (e >> 1);
        int jj = e & 1;
        int k = ch * 32 + kt * 8 + (lane & 3) + jj * 4;
        int n = nt * 8 + (lane >> 2);
        float v = 0.f;
        if (k < 4)          v = w1[k * H1N + n];
        else if (k < KTOT)  v = w1[(k + 1) * H1N + n];
        g_w1f[idx] = __uint_as_float(tf32r(v));
    }
}

// ---------------- fused main kernel ----------------
__global__ __launch_bounds__(NT, 3)
void fused_mma(const float* __restrict__ x,
               const float* __restrict__ w1,
               const float* __restrict__ b1,
               const float* __restrict__ w2,
               const float* __restrict__ b2,
               const float* __restrict__ w3,
               const float* __restrict__ b3,
               float* __restrict__ out)
{
    extern __shared__ __align__(16) char smem[];
    __shared__ __align__(16) float s_w2[H1N * H2N];
    __shared__ float s_w14[H1N], s_b1[H1N], s_b2[H2N], s_w3[H2N];
    __shared__ float s_den[MT], s_ceff[MT];
    __shared__ int   s_mi[MT];

    const uint32_t sdyn = smem_u32(smem);
    const int tid  = threadIdx.x;
    const int w    = tid >> 5;
    const int lane = tid & 31;
    const int rA   = lane >> 2;
    const int cA   = lane & 3;
    const int row0 = blockIdx.x * MT;

    // stage constants
#pragma unroll
    for (int i = tid; i < H1N * H2N; i += NT) s_w2[i] = __ldg(w2 + i);
    if (tid < H1N) { s_w14[tid] = __ldg(w1 + 4 * H1N + tid); s_b1[tid] = __ldg(b1 + tid); }
    if (tid < H2N) { s_b2[tid] = __ldg(b2 + tid); s_w3[tid] = __ldg(w3 + tid); }

    // B producer: 2 cp16 per thread per chunk (identity copy, pre-packed)
    auto produceB = [&](int ch) {
        if (ch < NCH) {
            const uint32_t slot = sdyn + (uint32_t)(ch & (NSTG - 1)) * B_ST;
            const float* src = g_w1f + (size_t)ch * 2048;
            cp16(slot + (uint32_t)tid * 16u, src + (size_t)tid * 4);
            cp16(slot + (uint32_t)(tid + NT) * 16u, src + (size_t)(tid + NT) * 4);
        }
        asm volatile("cp.async.commit_group;" ::: "memory");
    };

    // A loader: 16 floats in fragment layout (idx = kt*4 + hh*2 + r)
    const float* xp0 = x + (size_t)(row0 + w * 16 + rA) * DC + cA;
    const float* xp1 = xp0 + 8 * (size_t)DC;
    auto loadA = [&](int ch, float* dst) {
        const int kb = ch * KC;
        const float* p0 = xp0 + kb;
        const float* p1 = xp1 + kb;
#pragma unroll
        for (int kt = 0; kt < 4; kt++)
#pragma unroll
            for (int hh = 0; hh < 2; hh++) {
                const int ko = kt * 8 + hh * 4;
                const bool ok = (kb + ko + cA) < KTOT;
                dst[kt * 4 + hh * 2 + 0] = ok ? __ldg(p0 + ko) : 0.f;
                dst[kt * 4 + hh * 2 + 1] = ok ? __ldg(p1 + ko) : 0.f;
            }
    };

    float amv[2];
    int   ami[2];
    amv[0] = amv[1] = __int_as_float(0xff800000);
    ami[0] = ami[1] = 0;

    float acc[8][4];
#pragma unroll
    for (int nt = 0; nt < 8; nt++)
#pragma unroll
        for (int j = 0; j < 4; j++) acc[nt][j] = 0.f;

    float buf[2][16];

    // prologue
    produceB(0);
    produceB(1);
    produceB(2);
    loadA(0, buf[0]);
    if (cA == 0) {                    // density = x[row, 0] (chunk 0, kt0/hh0 slots)
        s_den[w * 16 + rA]     = buf[0][0];
        s_den[w * 16 + rA + 8] = buf[0][1];
    }

    // one chunk step; CUR/NXT selected by compile-time pb after unroll
    auto step = [&](int ch, int pb) {
        asm volatile("cp.async.wait_group 2;" ::: "memory");
        __syncthreads();              // B(ch) visible; slot (ch-1)&3 drained

        if (ch + 1 < NCH) loadA(ch + 1, buf[pb ^ 1]);
        produceB(ch + 3);

        const float* CUR = buf[pb];
        const uint32_t slotB = sdyn + (uint32_t)(ch & (NSTG - 1)) * B_ST;
        const uint32_t bbase = slotB + (uint32_t)lane * 64u;
        const int sw = cA ^ (rA & 1);
        const int kb = ch * KC;

#pragma unroll
        for (int kt = 0; kt < 4; kt++) {
            // argmax on raw f32 (k ascending within thread, matching reference tie rule)
#pragma unroll
            for (int hh = 0; hh < 2; hh++) {
                const int kg = kb + kt * 8 + cA + hh * 4;
                const float v0 = CUR[kt * 4 + hh * 2 + 0];
                const float v1 = CUR[kt * 4 + hh * 2 + 1];
                if ((unsigned)(kg - 4) < 1024u) {
                    if (v0 > amv[0]) { amv[0] = v0; ami[0] = kg - 4; }
                    if (v1 > amv[1]) { amv[1] = v1; ami[1] = kg - 4; }
                }
            }
            // transient tf32 fragment
            uint32_t a[4];
#pragma unroll
            for (int j = 0; j < 4; j++) a[j] = tf32r(CUR[kt * 4 + j]);

#pragma unroll
            for (int i = 0; i < 4; i++) {
                uint4 q;
                const uint32_t baddr = bbase + (uint32_t)kt * 2048u
                                     + (uint32_t)((i ^ sw) << 4);
                asm volatile("ld.shared.v4.u32 {%0,%1,%2,%3}, [%4];"
                             : "=r"(q.x), "=r"(q.y), "=r"(q.z), "=r"(q.w) : "r"(baddr));
                mma_tf32(acc[2 * i + 0], a, q.x, q.y);
                mma_tf32(acc[2 * i + 1], a, q.z, q.w);
            }
        }
    };

#pragma unroll 1
    for (int it = 0; it < 16; ++it) {     // chunks 0..31, ping-pong
        step(2 * it + 0, 0);
        step(2 * it + 1, 1);
    }
    step(32, 0);                          // last chunk

    // ---- argmax reduce across the 4 cA lanes ----
    __syncthreads();
#pragma unroll
    for (int d = 1; d < 4; d <<= 1) {
#pragma unroll
        for (int hf = 0; hf < 2; hf++) {
            float ov = __shfl_xor_sync(0xffffffffu, amv[hf], d);
            int   oi = __shfl_xor_sync(0xffffffffu, ami[hf], d);
            if (ov > amv[hf] || (ov == amv[hf] && oi < ami[hf])) { amv[hf] = ov; ami[hf] = oi; }
        }
    }
    if (cA == 0) {
        s_mi[w * 16 + rA]     = ami[0];
        s_mi[w * 16 + rA + 8] = ami[1];
    }
    __syncthreads();
    if (tid < MT) s_ceff[tid] = g_row_mean[s_mi[tid]] * s_den[tid];
    __syncthreads();

    // ---- layer-1 epilogue: +ceff*w1[4,:]+b1, relu; h -> dynamic smem (ring free) ----
    float* h = (float*)smem;
    {
        const int r1 = w * 16 + rA;
        const int cb = cA * 2;
        const float ce0 = s_ceff[r1];
        const float ce1 = s_ceff[r1 + 8];
#pragma unroll
        for (int nt = 0; nt < 8; nt++) {
            const int c = nt * 8 + cb;
            const float w0 = s_w14[c], w1v = s_w14[c + 1];
            const float q0 = s_b1[c],  q1  = s_b1[c + 1];
            float2 top, bot;
            top.x = fmaxf(acc[nt][0] + ce0 * w0 + q0, 0.f);
            top.y = fmaxf(acc[nt][1] + ce0 * w1v + q1, 0.f);
            bot.x = fmaxf(acc[nt][2] + ce1 * w0 + q0, 0.f);
            bot.y = fmaxf(acc[nt][3] + ce1 * w1v + q1, 0.f);
            *reinterpret_cast<float2*>(h + (size_t)r1 * H_STRIDE + c) = top;
            *reinterpret_cast<float2*>(h + (size_t)(r1 + 8) * H_STRIDE + c) = bot;
        }
    }
    __syncthreads();

    // ---- layers 2 & 3: one thread per row ----
    if (tid < MT) {
        float a2[H2N];
#pragma unroll
        for (int j = 0; j < H2N; j++) a2[j] = s_b2[j];
        const float* hr = h + (size_t)tid * H_STRIDE;
#pragma unroll 4
        for (int k = 0; k < H1N; k++) {
            const float a = hr[k];
            const float4* w2r = reinterpret_cast<const float4*>(s_w2 + k * H2N);
#pragma unroll
            for (int qq = 0; qq < H2N / 4; qq++) {
                float4 w4 = w2r[qq];
                a2[qq * 4 + 0] += a * w4.x;
                a2[qq * 4 + 1] += a * w4.y;
                a2[qq * 4 + 2] += a * w4.z;
                a2[qq * 4 + 3] += a * w4.w;
            }
        }
        float o = __ldg(b3);
#pragma unroll
        for (int j = 0; j < H2N; j++)
            o += fmaxf(a2[j], 0.f) * s_w3[j];
        out[row0 + tid] = fmaxf(o, 0.f);
    }
}

// ---------------- launch (2 launches per call) ----------------
extern "C" void kernel_launch(void* const* d_in, const int* in_sizes, int n_in,
                              void* d_out, int out_size) {
    const float* x   = (const float*)d_in[0];
    const float* con = (const float*)d_in[1];
    const float* w1  = (const float*)d_in[2];
    const float* b1  = (const float*)d_in[3];
    const float* w2  = (const float*)d_in[4];
    const float* b2  = (const float*)d_in[5];
    const float* w3  = (const float*)d_in[6];
    const float* b3  = (const float*)d_in[7];
    float* out = (float*)d_out;

    cudaFuncSetAttribute(fused_mma, cudaFuncAttributeMaxDynamicSharedMemorySize, SMEM_DYN);

    prep_kernel<<<TT + (NCH * 2048 + 255) / 256, 256>>>(con, w1);
    fused_mma<<<NB / MT, NT, SMEM_DYN>>>(x, w1, b1, w2, b2, w3, b3, out);
}

// round 10
// speedup vs baseline: 1.3789x; 1.3789x over previous
#include <cuda_runtime.h>
#include <cstdint>

#define NB    131072
#define DC    1029
#define TT    1024
#define H1N   64
#define H2N   32
#define KTOT  1028
#define KC    32
#define NCH   33              // 33*32 = 1056 padded K
#define MT    128             // rows per CTA
#define NT    256             // 8 warps, each m16 x n64
#define NSLOT 8               // B ring slots (4 pairs in flight)
#define B_ST  8192            // bytes per B stage (2048 floats)
#define SMEM_DYN 65536        // 8*B_ST (also covers h staging 34816)
#define H_STRIDE 68

__device__ float g_row_mean[TT];
__device__ __align__(16) float g_w1f[NCH * 2048];   // pre-packed, pre-swizzled tf32 B frags

// ---------------- helpers ----------------
__device__ __forceinline__ uint32_t tf32r(float f) {
    uint32_t u;
    asm("cvt.rna.tf32.f32 %0, %1;" : "=r"(u) : "f"(f));
    return u;
}
__device__ __forceinline__ void mma_tf32(float* d, const uint32_t* a, uint32_t b0, uint32_t b1) {
    asm volatile(
        "mma.sync.aligned.m16n8k8.row.col.f32.tf32.tf32.f32 "
        "{%0,%1,%2,%3}, {%4,%5,%6,%7}, {%8,%9}, {%0,%1,%2,%3};"
        : "+f"(d[0]), "+f"(d[1]), "+f"(d[2]), "+f"(d[3])
        : "r"(a[0]), "r"(a[1]), "r"(a[2]), "r"(a[3]), "r"(b0), "r"(b1));
}
__device__ __forceinline__ uint32_t smem_u32(const void* p) {
    uint32_t a;
    asm("{ .reg .u64 t; cvta.to.shared.u64 t, %1; cvt.u32.u64 %0, t; }" : "=r"(a) : "l"(p));
    return a;
}
__device__ __forceinline__ void cp16(uint32_t dst, const float* src) {
    asm volatile("cp.async.ca.shared.global [%0], [%1], 16;"
                 :: "r"(dst), "l"(__cvta_generic_to_global(src)) : "memory");
}

// ---------------- merged prep kernel (identical pack layout to R5) ----------------
__global__ void prep_kernel(const float* __restrict__ con, const float* __restrict__ w1) {
    if (blockIdx.x < TT) {
        int t = blockIdx.x;
        float s = 0.f;
        for (int j = threadIdx.x; j < TT; j += blockDim.x)
            s += con[(size_t)t * TT + j];
#pragma unroll
        for (int o = 16; o > 0; o >>= 1) s += __shfl_down_sync(0xffffffffu, s, o);
        __shared__ float red[8];
        if ((threadIdx.x & 31) == 0) red[threadIdx.x >> 5] = s;
        __syncthreads();
        if (threadIdx.x == 0) {
            float tot = 0.f;
#pragma unroll
            for (int w = 0; w < 8; w++) tot += red[w];
            g_row_mean[t] = tot * (1.0f / (float)TT);
        }
    } else {
        int idx = (blockIdx.x - TT) * blockDim.x + threadIdx.x;
        if (idx >= NCH * 2048) return;
        int ch = idx >> 11;
        int w  = idx & 2047;
        int g  = w >> 2, e = w & 3;
        int kt = g >> 7;
        int lane = (g >> 2) & 31;
        int s = g & 3;
        int i = s ^ (lane & 3) ^ ((lane >> 2) & 1);
        int nt = 2 * i + (e >> 1);
        int jj = e & 1;
        int k = ch * 32 + kt * 8 + (lane & 3) + jj * 4;
        int n = nt * 8 + (lane >> 2);
        float v = 0.f;
        if (k < 4)          v = w1[k * H1N + n];
        else if (k < KTOT)  v = w1[(k + 1) * H1N + n];
        g_w1f[idx] = __uint_as_float(tf32r(v));
    }
}

// ---------------- fused main kernel ----------------
__global__ __launch_bounds__(NT, 2)
void fused_mma(const float* __restrict__ x,
               const float* __restrict__ w1,
               const float* __restrict__ b1,
               const float* __restrict__ w2,
               const float* __restrict__ b2,
               const float* __restrict__ w3,
               const float* __restrict__ b3,
               float* __restrict__ out)
{
    extern __shared__ __align__(16) char smem[];
    __shared__ __align__(16) float s_w2[H1N * H2N];
    __shared__ float s_w14[H1N], s_b1[H1N], s_b2[H2N], s_w3[H2N];
    __shared__ float s_den[MT], s_ceff[MT];
    __shared__ int   s_mi[MT];

    const uint32_t sdyn = smem_u32(smem);
    const int tid  = threadIdx.x;
    const int w    = tid >> 5;
    const int lane = tid & 31;
    const int rA   = lane >> 2;
    const int cA   = lane & 3;
    const int row0 = blockIdx.x * MT;

    // stage constants
#pragma unroll
    for (int i = tid; i < H1N * H2N; i += NT) s_w2[i] = __ldg(w2 + i);
    if (tid < H1N) { s_w14[tid] = __ldg(w1 + 4 * H1N + tid); s_b1[tid] = __ldg(b1 + tid); }
    if (tid < H2N) { s_b2[tid] = __ldg(b2 + tid); s_w3[tid] = __ldg(w3 + tid); }

    // B producer: one commit-group per 2-chunk pair
    auto producePair = [&](int pr) {
#pragma unroll
        for (int q = 0; q < 2; q++) {
            const int ch = 2 * pr + q;
            if (ch < NCH) {
                const uint32_t slot = sdyn + (uint32_t)(ch & (NSLOT - 1)) * B_ST;
                const float* src = g_w1f + (size_t)ch * 2048;
                cp16(slot + (uint32_t)tid * 16u, src + (size_t)tid * 4);
                cp16(slot + (uint32_t)(tid + NT) * 16u, src + (size_t)(tid + NT) * 4);
            }
        }
        asm volatile("cp.async.commit_group;" ::: "memory");
    };

    // A loader: 16 floats in fragment layout (idx = kt*4 + hh*2 + r)  — as R5
    const float* xp0 = x + (size_t)(row0 + w * 16 + rA) * DC + cA;
    const float* xp1 = xp0 + 8 * (size_t)DC;
    auto loadA = [&](int ch, float* dst) {
        const int kb = ch * KC;
#pragma unroll
        for (int kt = 0; kt < 4; kt++)
#pragma unroll
            for (int hh = 0; hh < 2; hh++) {
                const int kg = kb + kt * 8 + hh * 4;
                const bool ok = (kg + cA) < KTOT;
                dst[kt * 4 + hh * 2 + 0] = ok ? __ldg(xp0 + kg) : 0.f;
                dst[kt * 4 + hh * 2 + 1] = ok ? __ldg(xp1 + kg) : 0.f;
            }
    };

    float amv[2];
    int   ami[2];
    amv[0] = amv[1] = __int_as_float(0xff800000);
    ami[0] = ami[1] = 0;

    float acc[8][4];
#pragma unroll
    for (int nt = 0; nt < 8; nt++)
#pragma unroll
        for (int j = 0; j < 4; j++) acc[nt][j] = 0.f;

    // one chunk's consume: argmax + convert + B LDS + 32 MMAs  — as R5
    auto process = [&](int ch, const float* CUR) {
        const int kb = ch * KC;
#pragma unroll
        for (int kt = 0; kt < 4; kt++)
#pragma unroll
            for (int hh = 0; hh < 2; hh++) {
                const int kg = kb + kt * 8 + cA + hh * 4;
                const float v0 = CUR[kt * 4 + hh * 2 + 0];
                const float v1 = CUR[kt * 4 + hh * 2 + 1];
                if ((unsigned)(kg - 4) < 1024u) {
                    if (v0 > amv[0]) { amv[0] = v0; ami[0] = kg - 4; }
                    if (v1 > amv[1]) { amv[1] = v1; ami[1] = kg - 4; }
                }
            }
        if (ch == 0 && cA == 0) {
            s_den[w * 16 + rA]     = CUR[0];
            s_den[w * 16 + rA + 8] = CUR[1];
        }

        uint32_t au[16];
#pragma unroll
        for (int i = 0; i < 16; i++) au[i] = tf32r(CUR[i]);

        const uint32_t slotB = sdyn + (uint32_t)(ch & (NSLOT - 1)) * B_ST;
        const uint32_t bbase = slotB + (uint32_t)lane * 64u;
        const int sw = cA ^ (rA & 1);
#pragma unroll
        for (int kt = 0; kt < 4; kt++) {
            const uint32_t* a = au + kt * 4;
#pragma unroll
            for (int i = 0; i < 4; i++) {
                uint4 q;
                const uint32_t baddr = bbase + (uint32_t)kt * 2048u
                                     + (uint32_t)((i ^ sw) << 4);
                asm volatile("ld.shared.v4.u32 {%0,%1,%2,%3}, [%4];"
                             : "=r"(q.x), "=r"(q.y), "=r"(q.z), "=r"(q.w) : "r"(baddr));
                mma_tf32(acc[2 * i + 0], a, q.x, q.y);
                mma_tf32(acc[2 * i + 1], a, q.z, q.w);
            }
        }
    };

    float bufA[16], bufB[16];

    // prologue: 3 pairs (6 chunks) of B in flight; A chunk 0 in regs
    producePair(0);
    producePair(1);
    producePair(2);
    loadA(0, bufA);

#pragma unroll 1
    for (int t = 0; t < 17; ++t) {
        asm volatile("cp.async.wait_group 2;" ::: "memory");
        __syncthreads();               // pair t (chunks 2t,2t+1) visible; pair t-1 slots free

        producePair(t + 3);            // refill into pair t-1's slots

        const int c0 = 2 * t, c1 = 2 * t + 1;
        if (c1 < NCH) loadA(c1, bufB);
        process(c0, bufA);
        if (c1 < NCH) {
            if (c1 + 1 < NCH) loadA(c1 + 1, bufA);
            process(c1, bufB);
        }
    }

    // ---- argmax reduce across the 4 cA lanes ----
    __syncthreads();
#pragma unroll
    for (int d = 1; d < 4; d <<= 1) {
#pragma unroll
        for (int hf = 0; hf < 2; hf++) {
            float ov = __shfl_xor_sync(0xffffffffu, amv[hf], d);
            int   oi = __shfl_xor_sync(0xffffffffu, ami[hf], d);
            if (ov > amv[hf] || (ov == amv[hf] && oi < ami[hf])) { amv[hf] = ov; ami[hf] = oi; }
        }
    }
    if (cA == 0) {
        s_mi[w * 16 + rA]     = ami[0];
        s_mi[w * 16 + rA + 8] = ami[1];
    }
    __syncthreads();
    if (tid < MT) s_ceff[tid] = g_row_mean[s_mi[tid]] * s_den[tid];
    __syncthreads();

    // ---- layer-1 epilogue: +ceff*w1[4,:]+b1, relu; h -> dynamic smem ----
    float* h = (float*)smem;
    {
        const int r1 = w * 16 + rA;
        const int cb = cA * 2;
        const float ce0 = s_ceff[r1];
        const float ce1 = s_ceff[r1 + 8];
#pragma unroll
        for (int nt = 0; nt < 8; nt++) {
            const int c = nt * 8 + cb;
            const float w0 = s_w14[c], w1v = s_w14[c + 1];
            const float q0 = s_b1[c],  q1  = s_b1[c + 1];
            float2 top, bot;
            top.x = fmaxf(acc[nt][0] + ce0 * w0 + q0, 0.f);
            top.y = fmaxf(acc[nt][1] + ce0 * w1v + q1, 0.f);
            bot.x = fmaxf(acc[nt][2] + ce1 * w0 + q0, 0.f);
            bot.y = fmaxf(acc[nt][3] + ce1 * w1v + q1, 0.f);
            *reinterpret_cast<float2*>(h + (size_t)r1 * H_STRIDE + c) = top;
            *reinterpret_cast<float2*>(h + (size_t)(r1 + 8) * H_STRIDE + c) = bot;
        }
    }
    __syncthreads();

    // ---- layers 2 & 3: one thread per row ----
    if (tid < MT) {
        float a2[H2N];
#pragma unroll
        for (int j = 0; j < H2N; j++) a2[j] = s_b2[j];
        const float* hr = h + (size_t)tid * H_STRIDE;
#pragma unroll 4
        for (int k = 0; k < H1N; k++) {
            const float a = hr[k];
            const float4* w2r = reinterpret_cast<const float4*>(s_w2 + k * H2N);
#pragma unroll
            for (int qq = 0; qq < H2N / 4; qq++) {
                float4 w4 = w2r[qq];
                a2[qq * 4 + 0] += a * w4.x;
                a2[qq * 4 + 1] += a * w4.y;
                a2[qq * 4 + 2] += a * w4.z;
                a2[qq * 4 + 3] += a * w4.w;
            }
        }
        float o = __ldg(b3);
#pragma unroll
        for (int j = 0; j < H2N; j++)
            o += fmaxf(a2[j], 0.f) * s_w3[j];
        out[row0 + tid] = fmaxf(o, 0.f);
    }
}

// ---------------- launch (2 launches per call) ----------------
extern "C" void kernel_launch(void* const* d_in, const int* in_sizes, int n_in,
                              void* d_out, int out_size) {
    const float* x   = (const float*)d_in[0];
    const float* con = (const float*)d_in[1];
    const float* w1  = (const float*)d_in[2];
    const float* b1  = (const float*)d_in[3];
    const float* w2  = (const float*)d_in[4];
    const float* b2  = (const float*)d_in[5];
    const float* w3  = (const float*)d_in[6];
    const float* b3  = (const float*)d_in[7];
    float* out = (float*)d_out;

    cudaFuncSetAttribute(fused_mma, cudaFuncAttributeMaxDynamicSharedMemorySize, SMEM_DYN);

    prep_kernel<<<TT + (NCH * 2048 + 255) / 256, 256>>>(con, w1);
    fused_mma<<<NB / MT, NT, SMEM_DYN>>>(x, w1, b1, w2, b2, w3, b3, out);
}